// round 3
// baseline (speedup 1.0000x reference)
#include <cuda_runtime.h>
#include <math.h>

#define SEQN 320
#define HN   400
#define GN   1600
#define NBK  25          // blocks per direction in LSTM phase
#define NP1  321

// ---------------- scratch (static device globals; no allocation) ----------------
__device__ float g_x[SEQN * HN];            // [320][400] embeddings
__device__ float g_G0[2][SEQN * GN];        // layer0 input projections (fwd, bwd)
__device__ float g_G1[2][SEQN * GN];        // layer1 input projections
__device__ float g_y0[SEQN * 800];          // layer0 bilstm output
__device__ float g_hv[SEQN * 800];          // layer1 bilstm output
__device__ float g_A[SEQN * GN];            // hv @ w1a.T
__device__ float g_B[SEQN * GN];            // hv @ w1b.T
__device__ float g_hbuf[2 * HN];            // h broadcast buffer (per dir)
__device__ unsigned g_bar[4];               // barrier counters: [phase*2 + dir]

// ---------------- prep: zero barrier counters ----------------
__global__ void k_prep() {
    if (threadIdx.x < 4) g_bar[threadIdx.x] = 0u;
}

// ---------------- embedding gather ----------------
__global__ void k_embed(const int* __restrict__ words, const int* __restrict__ tags,
                        const float* __restrict__ wemb, const float* __restrict__ temb) {
    int idx = blockIdx.x * blockDim.x + threadIdx.x;
    if (idx >= SEQN * HN) return;
    int t = idx / HN, j = idx % HN;
    g_x[idx] = (j < 300) ? wemb[(size_t)words[t] * 300 + j]
                         : temb[(size_t)tags[t] * 100 + (j - 300)];
}

// ---------------- generic NT GEMM: C[320][1600] = X[320][K] * W[:,wofs:wofs+K].T + b1 + b2
// W row-major [1600][ldw]. 64x64 tile, 256 threads, 4x4 per thread, k-chunk 16.
__global__ void __launch_bounds__(256)
k_gemm(const float* __restrict__ X, int ldx,
       const float* __restrict__ W, int ldw, int wofs,
       const float* __restrict__ b1, const float* __restrict__ b2,
       float* __restrict__ C, int K) {
    __shared__ __align__(16) float Xs[16][64];
    __shared__ __align__(16) float Ws[16][64];
    int tid = threadIdx.x;
    int tx = tid & 15, ty = tid >> 4;
    int row0 = blockIdx.x * 64, col0 = blockIdx.y * 64;
    int lk = tid & 15, lm0 = tid >> 4;

    float acc[4][4] = {};

    for (int k0 = 0; k0 < K; k0 += 16) {
#pragma unroll
        for (int p = 0; p < 4; p++) {
            int m = lm0 + p * 16;
            Xs[lk][m] = X[(size_t)(row0 + m) * ldx + k0 + lk];
            Ws[lk][m] = W[(size_t)(col0 + m) * ldw + wofs + k0 + lk];
        }
        __syncthreads();
#pragma unroll
        for (int kk = 0; kk < 16; kk++) {
            float4 a = *reinterpret_cast<const float4*>(&Xs[kk][ty * 4]);
            float4 b = *reinterpret_cast<const float4*>(&Ws[kk][tx * 4]);
            float av[4] = {a.x, a.y, a.z, a.w};
            float bv[4] = {b.x, b.y, b.z, b.w};
#pragma unroll
            for (int i = 0; i < 4; i++)
#pragma unroll
                for (int j = 0; j < 4; j++)
                    acc[i][j] = fmaf(av[i], bv[j], acc[i][j]);
        }
        __syncthreads();
    }
#pragma unroll
    for (int i = 0; i < 4; i++) {
#pragma unroll
        for (int j = 0; j < 4; j++) {
            int n = col0 + tx * 4 + j;
            float bias = 0.f;
            if (b1) bias += b1[n];
            if (b2) bias += b2[n];
            C[(size_t)(row0 + ty * 4 + i) * GN + n] = acc[i][j] + bias;
        }
    }
}

// ---------------- persistent BiLSTM phase (one layer, both directions) ----------------
// grid: (NBK, 2). Block owns 16 h-dims -> 64 gates. 256 threads:
//   thread t: r = t>>4 (dim-in-block), c = t&15 (25-dim chunk of the 400-d dot).
// Weights (100 floats) pinned in registers for the whole sequence.
__device__ __forceinline__ float sigf(float x) { return 1.f / (1.f + expf(-x)); }

__global__ void __launch_bounds__(256, 1)
k_lstm(const float* __restrict__ whh_f, const float* __restrict__ whh_b,
       const float* __restrict__ h0, const float* __restrict__ c0, int layer) {
    const int dir = blockIdx.y;
    const float* G   = (layer == 0) ? g_G0[dir] : g_G1[dir];
    float*       Y   = (layer == 0) ? g_y0 : g_hv;
    const float* whh = dir ? whh_b : whh_f;
    float*       hb  = g_hbuf + dir * HN;
    unsigned*    cnt = g_bar + layer * 2 + dir;
    const float* h0row = h0 + (size_t)(2 * layer + dir) * HN;
    const float* c0row = c0 + (size_t)(2 * layer + dir) * HN;

    const int tid = threadIdx.x;
    const int r   = tid >> 4;       // 0..15
    const int cch = tid & 15;       // 0..15, chunk of 25 dims
    const int dim = blockIdx.x * 16 + r;
    const bool leader = (cch == 0);

    // load recurrent weights into registers (once)
    float wI[25], wF[25], wG[25], wO[25];
    {
        const float* pI = whh + (size_t)(dim)        * HN + cch * 25;
        const float* pF = whh + (size_t)(400 + dim)  * HN + cch * 25;
        const float* pG = whh + (size_t)(800 + dim)  * HN + cch * 25;
        const float* pO = whh + (size_t)(1200 + dim) * HN + cch * 25;
#pragma unroll
        for (int d = 0; d < 25; d++) { wI[d] = pI[d]; wF[d] = pF[d]; wG[d] = pG[d]; wO[d] = pO[d]; }
    }

    float cst = leader ? c0row[dim] : 0.f;

    __shared__ float sh_h[HN];

    for (int s = 0; s < SEQN; ++s) {
        // ---- wait for previous step from all blocks of this direction ----
        if (s > 0) {
            if (tid == 0) {
                unsigned target = (unsigned)(NBK * s);
                unsigned v;
                do {
                    asm volatile("ld.acquire.gpu.global.u32 %0, [%1];"
                                 : "=r"(v) : "l"(cnt) : "memory");
                } while (v < target);
            }
            __syncthreads();
            for (int i = tid; i < HN; i += 256) {
                float v;
                asm volatile("ld.global.cg.f32 %0, [%1];" : "=f"(v) : "l"(hb + i) : "memory");
                sh_h[i] = v;
            }
        } else {
            for (int i = tid; i < HN; i += 256) sh_h[i] = h0row[i];
        }
        __syncthreads();

        const int t = dir ? (SEQN - 1 - s) : s;

        // prefetch input-projection gate values (leader only, independent of h)
        float gi = 0.f, gf = 0.f, gg = 0.f, go = 0.f;
        if (leader) {
            const float* grow = G + (size_t)t * GN;
            gi = __ldg(grow + dim);
            gf = __ldg(grow + 400 + dim);
            gg = __ldg(grow + 800 + dim);
            go = __ldg(grow + 1200 + dim);
        }

        // ---- partial dot products over this thread's 25-dim chunk ----
        float ai = 0.f, af = 0.f, ag = 0.f, ao = 0.f;
        const float* hp = &sh_h[cch * 25];
#pragma unroll
        for (int d = 0; d < 25; d++) {
            float hv = hp[d];
            ai = fmaf(wI[d], hv, ai);
            af = fmaf(wF[d], hv, af);
            ag = fmaf(wG[d], hv, ag);
            ao = fmaf(wO[d], hv, ao);
        }
        // reduce across the 16 chunk-lanes (aligned 16-lane groups within warp)
#pragma unroll
        for (int m = 8; m >= 1; m >>= 1) {
            ai += __shfl_xor_sync(0xffffffffu, ai, m);
            af += __shfl_xor_sync(0xffffffffu, af, m);
            ag += __shfl_xor_sync(0xffffffffu, ag, m);
            ao += __shfl_xor_sync(0xffffffffu, ao, m);
        }

        if (leader) {
            gi = sigf(gi + ai);
            gf = sigf(gf + af);
            go = sigf(go + ao);
            float gcv = tanhf(gg + ag);
            cst = gf * cst + gi * gcv;
            float hN = go * tanhf(cst);
            Y[(size_t)t * 800 + dir * HN + dim] = hN;
            hb[dim] = hN;
            __threadfence();
        }
        __syncthreads();
        if (tid == 0) {
            asm volatile("red.release.gpu.global.add.u32 [%0], %1;"
                         :: "l"(cnt), "r"(1u) : "memory");
        }
    }
}

// ---------------- output border (row 0 / col 0, corner) ----------------
__global__ void k_border(float* __restrict__ out) {
    int i = threadIdx.x;
    if (i < NP1) {
        out[i] = (i == 0) ? 1.f : 0.f;
        if (i > 0) out[(size_t)i * NP1] = 0.f;
    }
}

// ---------------- pairwise scorer ----------------
// scores[i][j] = b2 + sum_k relu(A[i,k] + B[j,k] + b1[k]) * w2[k]; diag zeroed.
__global__ void __launch_bounds__(256)
k_scores(const float* __restrict__ b1v, const float* __restrict__ w2,
         const float* __restrict__ b2, float* __restrict__ out) {
    __shared__ float As[32][65];
    __shared__ float Bs[32][65];
    __shared__ float w2s[64];
    int tid = threadIdx.x;
    int tx = tid & 15, ty = tid >> 4;
    int i0 = blockIdx.y * 32, j0 = blockIdx.x * 32;

    float acc[2][2] = {};

    for (int k0 = 0; k0 < GN; k0 += 64) {
        int c = tid & 63;
        int rbase = tid >> 6;      // 0..3
        float bb = __ldg(b1v + k0 + c);
#pragma unroll
        for (int p = 0; p < 8; p++) {
            int rr = rbase + p * 4;
            As[rr][c] = g_A[(size_t)(i0 + rr) * GN + k0 + c] + bb;
            Bs[rr][c] = g_B[(size_t)(j0 + rr) * GN + k0 + c];
        }
        if (tid < 64) w2s[tid] = w2[k0 + tid];
        __syncthreads();
#pragma unroll 8
        for (int kk = 0; kk < 64; kk++) {
            float w  = w2s[kk];
            float a0 = As[2 * ty][kk],     a1 = As[2 * ty + 1][kk];
            float b0 = Bs[2 * tx][kk],     b1_ = Bs[2 * tx + 1][kk];
            acc[0][0] = fmaf(fmaxf(a0 + b0, 0.f), w, acc[0][0]);
            acc[0][1] = fmaf(fmaxf(a0 + b1_, 0.f), w, acc[0][1]);
            acc[1][0] = fmaf(fmaxf(a1 + b0, 0.f), w, acc[1][0]);
            acc[1][1] = fmaf(fmaxf(a1 + b1_, 0.f), w, acc[1][1]);
        }
        __syncthreads();
    }
    float bb2 = __ldg(b2);
#pragma unroll
    for (int ii = 0; ii < 2; ii++)
#pragma unroll
        for (int jj = 0; jj < 2; jj++) {
            int i = i0 + 2 * ty + ii, j = j0 + 2 * tx + jj;
            float v = acc[ii][jj] + bb2;
            if (i == j) v = 0.f;
            out[(size_t)(i + 1) * NP1 + (j + 1)] = v;
        }
}

// ---------------- launch ----------------
extern "C" void kernel_launch(void* const* d_in, const int* in_sizes, int n_in,
                              void* d_out, int out_size) {
    const int*   words    = (const int*)  d_in[0];
    const int*   tags     = (const int*)  d_in[1];
    // d_in[2] = arcs (unused by reference)
    const float* wemb     = (const float*)d_in[3];
    const float* temb     = (const float*)d_in[4];
    const float* h0       = (const float*)d_in[5];
    const float* c0       = (const float*)d_in[6];
    const float* w_ih_l0  = (const float*)d_in[7];
    const float* w_hh_l0  = (const float*)d_in[8];
    const float* b_ih_l0  = (const float*)d_in[9];
    const float* b_hh_l0  = (const float*)d_in[10];
    const float* w_ih_l0r = (const float*)d_in[11];
    const float* w_hh_l0r = (const float*)d_in[12];
    const float* b_ih_l0r = (const float*)d_in[13];
    const float* b_hh_l0r = (const float*)d_in[14];
    const float* w_ih_l1  = (const float*)d_in[15];
    const float* w_hh_l1  = (const float*)d_in[16];
    const float* b_ih_l1  = (const float*)d_in[17];
    const float* b_hh_l1  = (const float*)d_in[18];
    const float* w_ih_l1r = (const float*)d_in[19];
    const float* w_hh_l1r = (const float*)d_in[20];
    const float* b_ih_l1r = (const float*)d_in[21];
    const float* b_hh_l1r = (const float*)d_in[22];
    const float* mlp_w1   = (const float*)d_in[23];
    const float* mlp_b1   = (const float*)d_in[24];
    const float* mlp_w2   = (const float*)d_in[25];
    const float* mlp_b2   = (const float*)d_in[26];
    float* out = (float*)d_out;

    float *px, *pG0, *pG1, *py0, *phv, *pA, *pB;
    cudaGetSymbolAddress((void**)&px,  g_x);
    cudaGetSymbolAddress((void**)&pG0, g_G0);
    cudaGetSymbolAddress((void**)&pG1, g_G1);
    cudaGetSymbolAddress((void**)&py0, g_y0);
    cudaGetSymbolAddress((void**)&phv, g_hv);
    cudaGetSymbolAddress((void**)&pA,  g_A);
    cudaGetSymbolAddress((void**)&pB,  g_B);
    float* pG0f = pG0;
    float* pG0b = pG0 + (size_t)SEQN * GN;
    float* pG1f = pG1;
    float* pG1b = pG1 + (size_t)SEQN * GN;

    dim3 gg(5, 25);   // 320/64 x 1600/64

    k_prep<<<1, 32>>>();
    k_embed<<<(SEQN * HN + 255) / 256, 256>>>(words, tags, wemb, temb);

    // layer0 input projections (bias folded)
    k_gemm<<<gg, 256>>>(px, HN, w_ih_l0,  HN, 0, b_ih_l0,  b_hh_l0,  pG0f, HN);
    k_gemm<<<gg, 256>>>(px, HN, w_ih_l0r, HN, 0, b_ih_l0r, b_hh_l0r, pG0b, HN);

    k_lstm<<<dim3(NBK, 2), 256>>>(w_hh_l0, w_hh_l0r, h0, c0, 0);

    // layer1 input projections
    k_gemm<<<gg, 256>>>(py0, 800, w_ih_l1,  800, 0, b_ih_l1,  b_hh_l1,  pG1f, 800);
    k_gemm<<<gg, 256>>>(py0, 800, w_ih_l1r, 800, 0, b_ih_l1r, b_hh_l1r, pG1b, 800);

    k_lstm<<<dim3(NBK, 2), 256>>>(w_hh_l1, w_hh_l1r, h0, c0, 1);

    // MLP projections: A = hv @ w1a.T, B = hv @ w1b.T (bias added in scorer)
    k_gemm<<<gg, 256>>>(phv, 800, mlp_w1, GN, 0,   nullptr, nullptr, pA, 800);
    k_gemm<<<gg, 256>>>(phv, 800, mlp_w1, GN, 800, nullptr, nullptr, pB, 800);

    k_border<<<1, 352>>>(out);
    k_scores<<<dim3(10, 10), 256>>>(mlp_b1, mlp_w2, mlp_b2, out);
}

// round 8
// speedup vs baseline: 1.5670x; 1.5670x over previous
#include <cuda_runtime.h>
#include <stdint.h>
#include <math.h>

#define SEQN 320
#define HN   400
#define GN   1600
#define NP1  321
#define CLU  16          // CTAs per direction (cluster size, non-portable)
#define DPC  25          // h-dims per CTA
#define TPB  416         // 13 full warps; 26 groups of 16 lanes (group 25 is dummy)

// ---------------- scratch (static device globals; no allocation) ----------------
__device__ float g_x[SEQN * HN];            // [320][400] embeddings
__device__ float g_G0[2][SEQN * GN];        // layer0 input projections (fwd, bwd)
__device__ float g_G1[2][SEQN * GN];        // layer1 input projections
__device__ float g_y0[SEQN * 800];          // layer0 bilstm output
__device__ float g_hv[SEQN * 800];          // layer1 bilstm output
__device__ float g_A[SEQN * GN];            // hv @ w1a.T
__device__ float g_B[SEQN * GN];            // hv @ w1b.T

// ---------------- embedding gather ----------------
__global__ void k_embed(const int* __restrict__ words, const int* __restrict__ tags,
                        const float* __restrict__ wemb, const float* __restrict__ temb) {
    int idx = blockIdx.x * blockDim.x + threadIdx.x;
    if (idx >= SEQN * HN) return;
    int t = idx / HN, j = idx % HN;
    g_x[idx] = (j < 300) ? wemb[(size_t)words[t] * 300 + j]
                         : temb[(size_t)tags[t] * 100 + (j - 300)];
}

// ---------------- fused dual NT GEMM: two independent problems via blockIdx.z ----
// C[320][1600] = X[320][K] * W[:, wofs:wofs+K].T + b1 + b2
__global__ void __launch_bounds__(256)
k_gemm2(const float* __restrict__ X, int ldx,
        const float* __restrict__ W0, const float* __restrict__ W1, int ldw,
        int wofs0, int wofs1,
        const float* __restrict__ b1a, const float* __restrict__ b1b,
        const float* __restrict__ b2a, const float* __restrict__ b2b,
        float* __restrict__ C0, float* __restrict__ C1, int K) {
    const float* W   = blockIdx.z ? W1 : W0;
    const int   wofs = blockIdx.z ? wofs1 : wofs0;
    const float* b1  = blockIdx.z ? b1b : b1a;
    const float* b2  = blockIdx.z ? b2b : b2a;
    float*       C   = blockIdx.z ? C1 : C0;

    __shared__ __align__(16) float Xs[16][64];
    __shared__ __align__(16) float Ws[16][64];
    int tid = threadIdx.x;
    int tx = tid & 15, ty = tid >> 4;
    int row0 = blockIdx.x * 64, col0 = blockIdx.y * 64;
    int lk = tid & 15, lm0 = tid >> 4;

    float acc[4][4] = {};

    for (int k0 = 0; k0 < K; k0 += 16) {
#pragma unroll
        for (int p = 0; p < 4; p++) {
            int m = lm0 + p * 16;
            Xs[lk][m] = X[(size_t)(row0 + m) * ldx + k0 + lk];
            Ws[lk][m] = W[(size_t)(col0 + m) * ldw + wofs + k0 + lk];
        }
        __syncthreads();
#pragma unroll
        for (int kk = 0; kk < 16; kk++) {
            float4 a = *reinterpret_cast<const float4*>(&Xs[kk][ty * 4]);
            float4 b = *reinterpret_cast<const float4*>(&Ws[kk][tx * 4]);
            float av[4] = {a.x, a.y, a.z, a.w};
            float bv[4] = {b.x, b.y, b.z, b.w};
#pragma unroll
            for (int i = 0; i < 4; i++)
#pragma unroll
                for (int j = 0; j < 4; j++)
                    acc[i][j] = fmaf(av[i], bv[j], acc[i][j]);
        }
        __syncthreads();
    }
#pragma unroll
    for (int i = 0; i < 4; i++) {
#pragma unroll
        for (int j = 0; j < 4; j++) {
            int n = col0 + tx * 4 + j;
            float bias = 0.f;
            if (b1) bias += b1[n];
            if (b2) bias += b2[n];
            C[(size_t)(row0 + ty * 4 + i) * GN + n] = acc[i][j] + bias;
        }
    }
}

// ---------------- cluster BiLSTM ----------------
__device__ __forceinline__ float sig_fast(float x) {
    return __fdividef(1.f, 1.f + __expf(-x));
}
__device__ __forceinline__ float tanh_fast(float x) {
    // tanh(x) = 2*sigmoid(2x) - 1
    return fmaf(2.f, __fdividef(1.f, 1.f + __expf(-2.f * x)), -1.f);
}
__device__ __forceinline__ uint32_t s2u(const void* p) {
    uint32_t a;
    asm("{ .reg .u64 t; cvta.to.shared.u64 t, %1; cvt.u32.u64 %0, t; }" : "=r"(a) : "l"(p));
    return a;
}
__device__ __forceinline__ void dsmem_store_f32(uint32_t local_addr, int rank, float v) {
    uint32_t remote;
    asm volatile("mapa.shared::cluster.u32 %0, %1, %2;" : "=r"(remote) : "r"(local_addr), "r"(rank));
    asm volatile("st.shared::cluster.f32 [%0], %1;" :: "r"(remote), "f"(v) : "memory");
}

// grid (32), cluster (16): blocks 0-15 = forward cluster, 16-31 = backward cluster.
// CTA owns 25 h-dims; thread t: group = t>>4 (dim), lane = t&15 (25-elem chunk of h).
// Recurrent weights (100 floats/thread) register-resident for all 320 steps.
// h double-buffered in SMEM; leaders broadcast new h to all 16 CTAs via DSMEM;
// one cluster barrier per step.
__global__ void __launch_bounds__(TPB, 1)
k_lstm(const float* __restrict__ whh_f, const float* __restrict__ whh_b,
       const float* __restrict__ h0, const float* __restrict__ c0, int layer) {
    const int dir = blockIdx.x >> 4;
    const int cta = blockIdx.x & 15;
    const float* G   = (layer == 0) ? g_G0[dir] : g_G1[dir];
    float*       Y   = (layer == 0) ? g_y0 : g_hv;
    const float* whh = dir ? whh_b : whh_f;
    const float* h0row = h0 + (size_t)(2 * layer + dir) * HN;
    const float* c0row = c0 + (size_t)(2 * layer + dir) * HN;

    const int tid = threadIdx.x;
    const int grp = tid >> 4;        // 0..25 (25 = dummy group)
    const int lc  = tid & 15;        // chunk id
    const bool active = grp < DPC;
    const int dim = cta * DPC + grp; // global h-dim when active
    const bool leader = active && (lc == 0);

    __shared__ __align__(16) float sh_h[2][HN];

    // register-resident recurrent weights
    float wI[25], wF[25], wGc[25], wO[25];
    if (active) {
        const float* pI = whh + (size_t)(dim)        * HN + lc * 25;
        const float* pF = whh + (size_t)(400 + dim)  * HN + lc * 25;
        const float* pG = whh + (size_t)(800 + dim)  * HN + lc * 25;
        const float* pO = whh + (size_t)(1200 + dim) * HN + lc * 25;
#pragma unroll
        for (int d = 0; d < 25; d++) {
            wI[d] = __ldg(pI + d); wF[d] = __ldg(pF + d);
            wGc[d] = __ldg(pG + d); wO[d] = __ldg(pO + d);
        }
    } else {
#pragma unroll
        for (int d = 0; d < 25; d++) { wI[d] = 0.f; wF[d] = 0.f; wGc[d] = 0.f; wO[d] = 0.f; }
    }

    float cst = leader ? __ldg(c0row + dim) : 0.f;

    // init buffer 0 with h0 (each CTA fills its own copy)
    for (int i = tid; i < HN; i += TPB) sh_h[0][i] = h0row[i];
    __syncthreads();

    const uint32_t h_base = s2u(&sh_h[0][0]);

    // prefetch G gates for step 0
    float gi = 0.f, gf = 0.f, gg = 0.f, go = 0.f;
    if (leader) {
        const float* gr = G + (size_t)(dir ? SEQN - 1 : 0) * GN + dim;
        gi = __ldg(gr); gf = __ldg(gr + 400); gg = __ldg(gr + 800); go = __ldg(gr + 1200);
    }

    for (int s = 0; s < SEQN; ++s) {
        const int buf = s & 1;
        const int t = dir ? (SEQN - 1 - s) : s;

        // partial dot products over this lane's 25-element chunk
        float ai = 0.f, af = 0.f, ag = 0.f, ao = 0.f;
        const float* hp = &sh_h[buf][lc * 25];
#pragma unroll
        for (int d = 0; d < 25; d++) {
            float hv = hp[d];
            ai = fmaf(wI[d], hv, ai);
            af = fmaf(wF[d], hv, af);
            ag = fmaf(wGc[d], hv, ag);
            ao = fmaf(wO[d], hv, ao);
        }
        // reduce across the 16 lanes of the group (xor<=15 stays within half-warp)
#pragma unroll
        for (int m = 8; m >= 1; m >>= 1) {
            ai += __shfl_xor_sync(0xffffffffu, ai, m);
            af += __shfl_xor_sync(0xffffffffu, af, m);
            ag += __shfl_xor_sync(0xffffffffu, ag, m);
            ao += __shfl_xor_sync(0xffffffffu, ao, m);
        }

        if (leader) {
            float I = sig_fast(gi + ai);
            float F = sig_fast(gf + af);
            float O = sig_fast(go + ao);
            float Gv = tanh_fast(gg + ag);
            cst = fmaf(F, cst, I * Gv);
            float hN = O * tanh_fast(cst);
            Y[(size_t)t * 800 + dir * HN + dim] = hN;
            // broadcast hN into every cluster CTA's next h buffer
            uint32_t laddr = h_base + (uint32_t)(((buf ^ 1) * HN + dim) * 4);
#pragma unroll
            for (int r = 0; r < CLU; r++) dsmem_store_f32(laddr, r, hN);
        }

        // prefetch next step's G gates (independent of h; hides post-barrier L2 latency)
        if (leader && s + 1 < SEQN) {
            const int tn = dir ? (SEQN - 2 - s) : (s + 1);
            const float* gr = G + (size_t)tn * GN + dim;
            gi = __ldg(gr); gf = __ldg(gr + 400); gg = __ldg(gr + 800); go = __ldg(gr + 1200);
        }

        // cluster barrier: release DSMEM stores, acquire before next step's reads
        asm volatile("barrier.cluster.arrive.aligned;" ::: "memory");
        asm volatile("barrier.cluster.wait.aligned;" ::: "memory");
    }
}

// ---------------- output border (row 0 / col 0, corner) ----------------
__global__ void k_border(float* __restrict__ out) {
    int i = threadIdx.x;
    if (i < NP1) {
        out[i] = (i == 0) ? 1.f : 0.f;
        if (i > 0) out[(size_t)i * NP1] = 0.f;
    }
}

// ---------------- pairwise scorer ----------------
__global__ void __launch_bounds__(256)
k_scores(const float* __restrict__ b1v, const float* __restrict__ w2,
         const float* __restrict__ b2, float* __restrict__ out) {
    __shared__ float As[32][65];
    __shared__ float Bs[32][65];
    __shared__ float w2s[64];
    int tid = threadIdx.x;
    int tx = tid & 15, ty = tid >> 4;
    int i0 = blockIdx.y * 32, j0 = blockIdx.x * 32;

    float acc[2][2] = {};

    for (int k0 = 0; k0 < GN; k0 += 64) {
        int c = tid & 63;
        int rbase = tid >> 6;
        float bb = __ldg(b1v + k0 + c);
#pragma unroll
        for (int p = 0; p < 8; p++) {
            int rr = rbase + p * 4;
            As[rr][c] = g_A[(size_t)(i0 + rr) * GN + k0 + c] + bb;
            Bs[rr][c] = g_B[(size_t)(j0 + rr) * GN + k0 + c];
        }
        if (tid < 64) w2s[tid] = w2[k0 + tid];
        __syncthreads();
#pragma unroll 8
        for (int kk = 0; kk < 64; kk++) {
            float w  = w2s[kk];
            float a0 = As[2 * ty][kk],  a1  = As[2 * ty + 1][kk];
            float b0 = Bs[2 * tx][kk],  b1_ = Bs[2 * tx + 1][kk];
            acc[0][0] = fmaf(fmaxf(a0 + b0, 0.f), w, acc[0][0]);
            acc[0][1] = fmaf(fmaxf(a0 + b1_, 0.f), w, acc[0][1]);
            acc[1][0] = fmaf(fmaxf(a1 + b0, 0.f), w, acc[1][0]);
            acc[1][1] = fmaf(fmaxf(a1 + b1_, 0.f), w, acc[1][1]);
        }
        __syncthreads();
    }
    float bb2 = __ldg(b2);
#pragma unroll
    for (int ii = 0; ii < 2; ii++)
#pragma unroll
        for (int jj = 0; jj < 2; jj++) {
            int i = i0 + 2 * ty + ii, j = j0 + 2 * tx + jj;
            float v = acc[ii][jj] + bb2;
            if (i == j) v = 0.f;
            out[(size_t)(i + 1) * NP1 + (j + 1)] = v;
        }
}

// ---------------- launch ----------------
extern "C" void kernel_launch(void* const* d_in, const int* in_sizes, int n_in,
                              void* d_out, int out_size) {
    const int*   words    = (const int*)  d_in[0];
    const int*   tags     = (const int*)  d_in[1];
    // d_in[2] = arcs (unused by reference)
    const float* wemb     = (const float*)d_in[3];
    const float* temb     = (const float*)d_in[4];
    const float* h0       = (const float*)d_in[5];
    const float* c0       = (const float*)d_in[6];
    const float* w_ih_l0  = (const float*)d_in[7];
    const float* w_hh_l0  = (const float*)d_in[8];
    const float* b_ih_l0  = (const float*)d_in[9];
    const float* b_hh_l0  = (const float*)d_in[10];
    const float* w_ih_l0r = (const float*)d_in[11];
    const float* w_hh_l0r = (const float*)d_in[12];
    const float* b_ih_l0r = (const float*)d_in[13];
    const float* b_hh_l0r = (const float*)d_in[14];
    const float* w_ih_l1  = (const float*)d_in[15];
    const float* w_hh_l1  = (const float*)d_in[16];
    const float* b_ih_l1  = (const float*)d_in[17];
    const float* b_hh_l1  = (const float*)d_in[18];
    const float* w_ih_l1r = (const float*)d_in[19];
    const float* w_hh_l1r = (const float*)d_in[20];
    const float* b_ih_l1r = (const float*)d_in[21];
    const float* b_hh_l1r = (const float*)d_in[22];
    const float* mlp_w1   = (const float*)d_in[23];
    const float* mlp_b1   = (const float*)d_in[24];
    const float* mlp_w2   = (const float*)d_in[25];
    const float* mlp_b2   = (const float*)d_in[26];
    float* out = (float*)d_out;

    float *px, *pG0, *pG1, *py0, *phv, *pA, *pB;
    cudaGetSymbolAddress((void**)&px,  g_x);
    cudaGetSymbolAddress((void**)&pG0, g_G0);
    cudaGetSymbolAddress((void**)&pG1, g_G1);
    cudaGetSymbolAddress((void**)&py0, g_y0);
    cudaGetSymbolAddress((void**)&phv, g_hv);
    cudaGetSymbolAddress((void**)&pA,  g_A);
    cudaGetSymbolAddress((void**)&pB,  g_B);
    float* pG0f = pG0;
    float* pG0b = pG0 + (size_t)SEQN * GN;
    float* pG1f = pG1;
    float* pG1b = pG1 + (size_t)SEQN * GN;

    // allow 16-CTA clusters for the LSTM kernel (idempotent)
    static int attr_done = 0;
    if (!attr_done) {
        cudaFuncSetAttribute(k_lstm, cudaFuncAttributeNonPortableClusterSizeAllowed, 1);
        attr_done = 1;
    }
    cudaLaunchConfig_t cfg = {};
    cfg.gridDim  = dim3(2 * CLU, 1, 1);
    cfg.blockDim = dim3(TPB, 1, 1);
    cfg.dynamicSmemBytes = 0;
    cfg.stream = 0;
    cudaLaunchAttribute lat[1];
    lat[0].id = cudaLaunchAttributeClusterDimension;
    lat[0].val.clusterDim.x = CLU;
    lat[0].val.clusterDim.y = 1;
    lat[0].val.clusterDim.z = 1;
    cfg.attrs = lat;
    cfg.numAttrs = 1;

    dim3 gg2(5, 25, 2);   // 320/64 x 1600/64 x 2 fused problems

    k_embed<<<(SEQN * HN + 255) / 256, 256>>>(words, tags, wemb, temb);

    // layer0 input projections (fwd + bwd fused)
    k_gemm2<<<gg2, 256>>>(px, HN, w_ih_l0, w_ih_l0r, HN, 0, 0,
                          b_ih_l0, b_ih_l0r, b_hh_l0, b_hh_l0r, pG0f, pG0b, HN);

    cudaLaunchKernelEx(&cfg, k_lstm, w_hh_l0, w_hh_l0r, h0, c0, 0);

    // layer1 input projections (fwd + bwd fused)
    k_gemm2<<<gg2, 256>>>(py0, 800, w_ih_l1, w_ih_l1r, 800, 0, 0,
                          b_ih_l1, b_ih_l1r, b_hh_l1, b_hh_l1r, pG1f, pG1b, 800);

    cudaLaunchKernelEx(&cfg, k_lstm, w_hh_l1, w_hh_l1r, h0, c0, 1);

    // MLP projections: A = hv @ w1a.T, B = hv @ w1b.T (bias added in scorer)
    k_gemm2<<<gg2, 256>>>(phv, 800, mlp_w1, mlp_w1, GN, 0, 800,
                          nullptr, nullptr, nullptr, nullptr, pA, pB, 800);

    k_border<<<1, 352>>>(out);
    k_scores<<<dim3(10, 10), 256>>>(mlp_b1, mlp_w2, mlp_b2, out);
}